// round 17
// baseline (speedup 1.0000x reference)
#include <cuda_runtime.h>

#define Bn   16
#define CIN  64
#define COUT 64
#define Hn   130
#define Wn   130
#define HOn  128
#define WOn  128
#define Gn   8
#define CPGn 8
#define OFFC 144   // G*2*K*K
#define HWo  16384 // 128*128
#define HWi  16900 // 130*130

// Intermediate feature map t = conv3x3(x, w1) + b1  : [16,64,128,128]
__device__ float g_t[(size_t)Bn * CIN * HOn * WOn];
// Transposed input: xt[b][g][y][x][c8] (grouped NHWC8)
__device__ float g_xt[(size_t)Bn * Gn * HWi * CPGn];

// ---- packed fp32x2 helpers (Blackwell FFMA2, PTX-only) ---------------------
__device__ __forceinline__ unsigned long long pack2(float v) {
    unsigned long long r;
    asm("mov.b64 %0, {%1, %1};" : "=l"(r) : "f"(v));
    return r;
}
__device__ __forceinline__ void ffma2(unsigned long long& a,
                                      unsigned long long w,
                                      unsigned long long v) {
    asm("fma.rn.f32x2 %0, %1, %2, %0;" : "+l"(a) : "l"(w), "l"(v));
}
__device__ __forceinline__ void unpack2(unsigned long long a, float& lo, float& hi) {
    asm("mov.b64 {%0, %1}, %2;" : "=f"(lo), "=f"(hi) : "l"(a));
}

// ---------------------------------------------------------------------------
// Kernel 0: transpose x [b, g*8+c, y, x] -> xt [b, g, y, x, c8].
// ---------------------------------------------------------------------------
__global__ __launch_bounds__(256) void transpose_kernel(const float* __restrict__ x)
{
    __shared__ float s[8][132];
    const int yy = blockIdx.x;
    const int g  = blockIdx.y;
    const int b  = blockIdx.z;
    const int tid = threadIdx.x;

    const size_t rbase = ((size_t)(b * CIN + g * CPGn)) * HWi + (size_t)yy * Wn;
    for (int e = tid; e < 8 * Wn; e += 256) {
        int c = e / Wn, xx = e - c * Wn;
        s[c][xx] = x[rbase + (size_t)c * HWi + xx];
    }
    __syncthreads();

    const size_t wbase = (((size_t)(b * Gn + g)) * HWi + (size_t)yy * Wn) * CPGn;
    for (int e = tid; e < 8 * Wn; e += 256) {
        int xx = e >> 3, c = e & 7;
        g_xt[wbase + e] = s[c][xx];
    }
}

// ---------------------------------------------------------------------------
// Kernel 1: 3x3 VALID conv, 64->64. Reg-neutral FFMA2 (round-9, 516us).
// ---------------------------------------------------------------------------
__global__ __launch_bounds__(256, 4) void conv3x3_kernel(
    const float* __restrict__ x, const float* __restrict__ w1,
    const float* __restrict__ b1)
{
    const int tx = threadIdx.x;
    const int ty = threadIdx.y;
    const int tid = ty * 32 + tx;
    const int tileX = blockIdx.x * 32;
    const int tileY = blockIdx.y * 16;
    const int b = blockIdx.z >> 2;
    const int coBase = (blockIdx.z & 3) * 16;

    __shared__ float s_in[2][18][36];
    __shared__ __align__(16) float s_w[2][9][16];

    unsigned long long acc0[8], acc1[8];
#pragma unroll
    for (int i = 0; i < 8; ++i) { acc0[i] = 0ull; acc1[i] = 0ull; }

    for (int ci0 = 0; ci0 < CIN; ci0 += 2) {
#pragma unroll
        for (int cc = 0; cc < 2; ++cc) {
            const float* xp = x + ((size_t)(b * CIN + ci0 + cc)) * HWi;
            for (int e = tid; e < 18 * 34; e += 256) {
                int r = e / 34, c = e - r * 34;
                s_in[cc][r][c] = xp[(tileY + r) * Wn + (tileX + c)];
            }
        }
        for (int e = tid; e < 288; e += 256) {
            int cc = e / 144;
            int k  = (e % 144) >> 4;
            int co = e & 15;
            s_w[cc][k][co] = w1[((size_t)(coBase + co) * CIN + ci0 + cc) * 9 + k];
        }
        __syncthreads();

#pragma unroll
        for (int cc = 0; cc < 2; ++cc) {
            float in[4][3];
#pragma unroll
            for (int r = 0; r < 4; ++r)
#pragma unroll
                for (int c = 0; c < 3; ++c)
                    in[r][c] = s_in[cc][ty * 2 + r][tx + c];

#pragma unroll
            for (int ky = 0; ky < 3; ++ky)
#pragma unroll
                for (int kx = 0; kx < 3; ++kx) {
                    unsigned long long i0 = pack2(in[ky][kx]);
                    unsigned long long i1 = pack2(in[ky + 1][kx]);
                    const ulonglong2* wp = (const ulonglong2*)s_w[cc][ky * 3 + kx];
#pragma unroll
                    for (int q = 0; q < 4; ++q) {
                        ulonglong2 w = wp[q];
                        ffma2(acc0[q * 2 + 0], w.x, i0);
                        ffma2(acc0[q * 2 + 1], w.y, i0);
                        ffma2(acc1[q * 2 + 0], w.x, i1);
                        ffma2(acc1[q * 2 + 1], w.y, i1);
                    }
                }
        }
        __syncthreads();
    }

    const int oy = tileY + ty * 2;
    const int ox = tileX + tx;
#pragma unroll
    for (int q = 0; q < 8; ++q) {
        float a0lo, a0hi, a1lo, a1hi;
        unpack2(acc0[q], a0lo, a0hi);
        unpack2(acc1[q], a1lo, a1hi);
        int co = coBase + q * 2;
        float bb0 = b1[co], bb1 = b1[co + 1];
        size_t base0 = ((size_t)(b * COUT + co)) * HWo;
        size_t base1 = base0 + HWo;
        g_t[base0 + (size_t)oy * WOn + ox]       = a0lo + bb0;
        g_t[base0 + (size_t)(oy + 1) * WOn + ox] = a1lo + bb0;
        g_t[base1 + (size_t)oy * WOn + ox]       = a0hi + bb1;
        g_t[base1 + (size_t)(oy + 1) * WOn + ox] = a1hi + bb1;
    }
}

// ---------------------------------------------------------------------------
// Kernel 2: 1x1 conv 64->144 (offset prediction), FFMA2 packed (reg-neutral).
// ---------------------------------------------------------------------------
__global__ __launch_bounds__(256, 2) void conv1x1_kernel(
    const float* __restrict__ w2, const float* __restrict__ b2,
    float* __restrict__ off)
{
    __shared__ __align__(16) float s_w[64 * 48];
    __shared__ float s_t[16][256];

    const int tid = threadIdx.x;
    const int coBase = blockIdx.y * 48;
    const int p0 = blockIdx.x * 256;
    const int b = p0 >> 14;
    const int hwBase = p0 & (HWo - 1);

    for (int e = tid; e < 64 * 48; e += 256) {
        int cin = e / 48, co = e - cin * 48;
        s_w[e] = w2[(size_t)(coBase + co) * CIN + cin];
    }

    unsigned long long acc[24];
#pragma unroll
    for (int i = 0; i < 24; ++i) acc[i] = 0ull;

    for (int chunk = 0; chunk < 4; ++chunk) {
        __syncthreads();
#pragma unroll
        for (int r = 0; r < 16; ++r)
            s_t[r][tid] = g_t[((size_t)(b * CIN + chunk * 16 + r)) * HWo + hwBase + tid];
        __syncthreads();
#pragma unroll
        for (int r = 0; r < 16; ++r) {
            unsigned long long tv = pack2(s_t[r][tid]);
            const ulonglong2* wp = (const ulonglong2*)(s_w + (chunk * 16 + r) * 48);
#pragma unroll
            for (int q = 0; q < 12; ++q) {
                ulonglong2 w = wp[q];
                ffma2(acc[q * 2 + 0], w.x, tv);
                ffma2(acc[q * 2 + 1], w.y, tv);
            }
        }
    }

    const int hw = hwBase + tid;
#pragma unroll
    for (int q = 0; q < 24; ++q) {
        float lo, hi;
        unpack2(acc[q], lo, hi);
        int co = coBase + q * 2;
        off[((size_t)(b * OFFC + co)) * HWo + hw]     = lo + b2[co];
        off[((size_t)(b * OFFC + co + 1)) * HWo + hw] = hi + b2[co + 1];
    }
}

// ---------------------------------------------------------------------------
// Kernel 3: deformable conv — TRUE software pipeline.
// iter ij: issue low-corner LDGs for tap ij+1 -> B(ij,c0..3) ->
//          bilinear low STS + issue high-corner LDGs -> B(ij,c4..7) ->
//          bilinear high STS -> barrier.
// Offsets rolled one tap ahead. ij loop NOT unrolled (I$).
// ---------------------------------------------------------------------------
__global__ __launch_bounds__(256, 2) void deform_kernel(
    const float* __restrict__ wd, const float* __restrict__ off,
    float* __restrict__ y)
{
    __shared__ __align__(16) float s_w[9 * 8 * 64];     // 18432 B [ij][c][co]
    __shared__ __align__(16) float s_v[2][8][256];      // 16384 B ping-pong

    const int tid  = threadIdx.x;          // 0..255
    const int lane = tid & 31;
    const int wid  = tid >> 5;             // 0..7
    const int hoBase = blockIdx.y * 8;
    const int woBase = blockIdx.x * 32;
    const int b  = blockIdx.z;

    const int ho = hoBase + wid;           // phase-A row
    const int wo = woBase + lane;          // phase-A col
    const size_t offPixBase = ((size_t)b * OFFC) * HWo + (size_t)ho * WOn + wo;

    // Phase-B tile coordinates
    const int wp = wid & 3;                          // px quadrant (64 px)
    const int wc = wid >> 2;                         // co half (32 co)
    const int coStart = wc * 32 + (lane >> 4) * 16;  // 16 co per thread
    const int pxBase  = wp * 64 + (lane & 15) * 4;   // 4 px per thread

    unsigned long long acc[8][4];   // [co-pair][px]
#pragma unroll
    for (int i = 0; i < 8; ++i)
#pragma unroll
        for (int k = 0; k < 4; ++k) acc[i][k] = 0ull;

    for (int g = 0; g < Gn; ++g) {
        const float* xg = g_xt + ((size_t)(b * Gn + g)) * HWi * CPGn;
        const size_t offG = offPixBase + (size_t)(g * 9 * 2) * HWo;

        // stage weights for this group (prev-group reads fenced by last barrier)
        for (int e = tid; e < 4608; e += 256) {
            int co = e & 63;
            int c  = (e >> 6) & 7;
            int ij = e >> 9;
            int i = ij / 3, j = ij - i * 3;
            s_w[e] = wd[(((size_t)co * CIN + g * CPGn + c) * 3 + i) * 3 + j];
        }

        // ---- prologue: tap 0 full gather -> buffer 0 ----
        {
            float dy = __ldg(off + offG);
            float dx = __ldg(off + offG + HWo);
            float py = dy + (float)ho;
            float px = dx + (float)wo;
            float y0f = floorf(py), x0f = floorf(px);
            float ly = py - y0f, lx = px - x0f;
            int y0 = (int)y0f, x0 = (int)x0f;
            int y1 = y0 + 1, x1 = x0 + 1;
            float vy0 = (y0 >= 0 && y0 < Hn) ? 1.f : 0.f;
            float vy1 = (y1 >= 0 && y1 < Hn) ? 1.f : 0.f;
            float vx0 = (x0 >= 0 && x0 < Wn) ? 1.f : 0.f;
            float vx1 = (x1 >= 0 && x1 < Wn) ? 1.f : 0.f;
            float w00 = (1.f - ly) * (1.f - lx) * vy0 * vx0;
            float w01 = (1.f - ly) * lx * vy0 * vx1;
            float w10 = ly * (1.f - lx) * vy1 * vx0;
            float w11 = ly * lx * vy1 * vx1;
            int yc0 = min(max(y0, 0), Hn - 1), yc1 = min(max(y1, 0), Hn - 1);
            int xc0 = min(max(x0, 0), Wn - 1), xc1 = min(max(x1, 0), Wn - 1);
            const float4* p00 = (const float4*)(xg + (size_t)(yc0 * Wn + xc0) * 8);
            const float4* p01 = (const float4*)(xg + (size_t)(yc0 * Wn + xc1) * 8);
            const float4* p10 = (const float4*)(xg + (size_t)(yc1 * Wn + xc0) * 8);
            const float4* p11 = (const float4*)(xg + (size_t)(yc1 * Wn + xc1) * 8);
            float4 a00 = __ldg(p00), a01 = __ldg(p01);
            float4 a10 = __ldg(p10), a11 = __ldg(p11);
            float4 b00 = __ldg(p00 + 1), b01 = __ldg(p01 + 1);
            float4 b10 = __ldg(p10 + 1), b11 = __ldg(p11 + 1);
            s_v[0][0][tid] = w00 * a00.x + w01 * a01.x + w10 * a10.x + w11 * a11.x;
            s_v[0][1][tid] = w00 * a00.y + w01 * a01.y + w10 * a10.y + w11 * a11.y;
            s_v[0][2][tid] = w00 * a00.z + w01 * a01.z + w10 * a10.z + w11 * a11.z;
            s_v[0][3][tid] = w00 * a00.w + w01 * a01.w + w10 * a10.w + w11 * a11.w;
            s_v[0][4][tid] = w00 * b00.x + w01 * b01.x + w10 * b10.x + w11 * b11.x;
            s_v[0][5][tid] = w00 * b00.y + w01 * b01.y + w10 * b10.y + w11 * b11.y;
            s_v[0][6][tid] = w00 * b00.z + w01 * b01.z + w10 * b10.z + w11 * b11.z;
            s_v[0][7][tid] = w00 * b00.w + w01 * b01.w + w10 * b10.w + w11 * b11.w;
        }
        // preload offsets for tap 1
        float dyC = __ldg(off + offG + 2 * HWo);
        float dxC = __ldg(off + offG + 3 * HWo);
        __syncthreads();

#pragma unroll 1
        for (int ij = 0; ij < 9; ++ij) {
            const bool hasNext = (ij < 8);

            // ---- issue next tap's LOW corner loads (before any B work) ----
            float nw00, nw01, nw10, nw11;
            const float4 *p00, *p01, *p10, *p11;
            float4 cl00, cl01, cl10, cl11;
            if (hasNext) {
                const int nt = ij + 1;
                const int ni = nt / 3, nj = nt - ni * 3;
                float py = dyC + (float)(ho + ni);
                float px = dxC + (float)(wo + nj);
                float y0f = floorf(py), x0f = floorf(px);
                float ly = py - y0f, lx = px - x0f;
                int y0 = (int)y0f, x0 = (int)x0f;
                int y1 = y0 + 1, x1 = x0 + 1;
                float vy0 = (y0 >= 0 && y0 < Hn) ? 1.f : 0.f;
                float vy1 = (y1 >= 0 && y1 < Hn) ? 1.f : 0.f;
                float vx0 = (x0 >= 0 && x0 < Wn) ? 1.f : 0.f;
                float vx1 = (x1 >= 0 && x1 < Wn) ? 1.f : 0.f;
                nw00 = (1.f - ly) * (1.f - lx) * vy0 * vx0;
                nw01 = (1.f - ly) * lx * vy0 * vx1;
                nw10 = ly * (1.f - lx) * vy1 * vx0;
                nw11 = ly * lx * vy1 * vx1;
                int yc0 = min(max(y0, 0), Hn - 1), yc1 = min(max(y1, 0), Hn - 1);
                int xc0 = min(max(x0, 0), Wn - 1), xc1 = min(max(x1, 0), Wn - 1);
                p00 = (const float4*)(xg + (size_t)(yc0 * Wn + xc0) * 8);
                p01 = (const float4*)(xg + (size_t)(yc0 * Wn + xc1) * 8);
                p10 = (const float4*)(xg + (size_t)(yc1 * Wn + xc0) * 8);
                p11 = (const float4*)(xg + (size_t)(yc1 * Wn + xc1) * 8);
                cl00 = __ldg(p00); cl01 = __ldg(p01);
                cl10 = __ldg(p10); cl11 = __ldg(p11);
                if (ij < 7) {   // roll offsets one more tap ahead
                    dyC = __ldg(off + offG + (size_t)((ij + 2) * 2) * HWo);
                    dxC = __ldg(off + offG + (size_t)((ij + 2) * 2 + 1) * HWo);
                }
            }

            const float (*svb)[256] = s_v[ij & 1];
            float (*svn)[256] = s_v[(ij + 1) & 1];
            const float* wij = s_w + ij * 512;

            // ---- Phase B, channels 0..3 (covers low-corner LDG latency) ----
#pragma unroll
            for (int c = 0; c < 4; ++c) {
                float4 vf = *(const float4*)&svb[c][pxBase];
                unsigned long long v0 = pack2(vf.x);
                unsigned long long v1 = pack2(vf.y);
                unsigned long long v2 = pack2(vf.z);
                unsigned long long v3 = pack2(vf.w);
                const ulonglong2* wrow = (const ulonglong2*)(wij + c * 64 + coStart);
                ulonglong2 wA = wrow[0], wB = wrow[1], wC = wrow[2], wD = wrow[3];
                ffma2(acc[0][0], wA.x, v0); ffma2(acc[0][1], wA.x, v1);
                ffma2(acc[0][2], wA.x, v2); ffma2(acc[0][3], wA.x, v3);
                ffma2(acc[1][0], wA.y, v0); ffma2(acc[1][1], wA.y, v1);
                ffma2(acc[1][2], wA.y, v2); ffma2(acc[1][3], wA.y, v3);
                ffma2(acc[2][0], wB.x, v0); ffma2(acc[2][1], wB.x, v1);
                ffma2(acc[2][2], wB.x, v2); ffma2(acc[2][3], wB.x, v3);
                ffma2(acc[3][0], wB.y, v0); ffma2(acc[3][1], wB.y, v1);
                ffma2(acc[3][2], wB.y, v2); ffma2(acc[3][3], wB.y, v3);
                ffma2(acc[4][0], wC.x, v0); ffma2(acc[4][1], wC.x, v1);
                ffma2(acc[4][2], wC.x, v2); ffma2(acc[4][3], wC.x, v3);
                ffma2(acc[5][0], wC.y, v0); ffma2(acc[5][1], wC.y, v1);
                ffma2(acc[5][2], wC.y, v2); ffma2(acc[5][3], wC.y, v3);
                ffma2(acc[6][0], wD.x, v0); ffma2(acc[6][1], wD.x, v1);
                ffma2(acc[6][2], wD.x, v2); ffma2(acc[6][3], wD.x, v3);
                ffma2(acc[7][0], wD.y, v0); ffma2(acc[7][1], wD.y, v1);
                ffma2(acc[7][2], wD.y, v2); ffma2(acc[7][3], wD.y, v3);
            }

            // ---- consume low corners -> STS; issue HIGH corner loads ----
            float4 ch00, ch01, ch10, ch11;
            if (hasNext) {
                svn[0][tid] = nw00 * cl00.x + nw01 * cl01.x + nw10 * cl10.x + nw11 * cl11.x;
                svn[1][tid] = nw00 * cl00.y + nw01 * cl01.y + nw10 * cl10.y + nw11 * cl11.y;
                svn[2][tid] = nw00 * cl00.z + nw01 * cl01.z + nw10 * cl10.z + nw11 * cl11.z;
                svn[3][tid] = nw00 * cl00.w + nw01 * cl01.w + nw10 * cl10.w + nw11 * cl11.w;
                ch00 = __ldg(p00 + 1); ch01 = __ldg(p01 + 1);
                ch10 = __ldg(p10 + 1); ch11 = __ldg(p11 + 1);
            }

            // ---- Phase B, channels 4..7 (covers high-corner LDG latency) ----
#pragma unroll
            for (int c = 4; c < 8; ++c) {
                float4 vf = *(const float4*)&svb[c][pxBase];
                unsigned long long v0 = pack2(vf.x);
                unsigned long long v1 = pack2(vf.y);
                unsigned long long v2 = pack2(vf.z);
                unsigned long long v3 = pack2(vf.w);
                const ulonglong2* wrow = (const ulonglong2*)(wij + c * 64 + coStart);
                ulonglong2 wA = wrow[0], wB = wrow[1], wC = wrow[2], wD = wrow[3];
                ffma2(acc[0][0], wA.x, v0); ffma2(acc[0][1], wA.x, v1);
                ffma2(acc[0][2], wA.x, v2); ffma2(acc[0][3], wA.x, v3);
                ffma2(acc[1][0], wA.y, v0); ffma2(acc[1][1], wA.y, v1);
                ffma2(acc[1][2], wA.y, v2); ffma2(acc[1][3], wA.y, v3);
                ffma2(acc[2][0], wB.x, v0); ffma2(acc[2][1], wB.x, v1);
                ffma2(acc[2][2], wB.x, v2); ffma2(acc[2][3], wB.x, v3);
                ffma2(acc[3][0], wB.y, v0); ffma2(acc[3][1], wB.y, v1);
                ffma2(acc[3][2], wB.y, v2); ffma2(acc[3][3], wB.y, v3);
                ffma2(acc[4][0], wC.x, v0); ffma2(acc[4][1], wC.x, v1);
                ffma2(acc[4][2], wC.x, v2); ffma2(acc[4][3], wC.x, v3);
                ffma2(acc[5][0], wC.y, v0); ffma2(acc[5][1], wC.y, v1);
                ffma2(acc[5][2], wC.y, v2); ffma2(acc[5][3], wC.y, v3);
                ffma2(acc[6][0], wD.x, v0); ffma2(acc[6][1], wD.x, v1);
                ffma2(acc[6][2], wD.x, v2); ffma2(acc[6][3], wD.x, v3);
                ffma2(acc[7][0], wD.y, v0); ffma2(acc[7][1], wD.y, v1);
                ffma2(acc[7][2], wD.y, v2); ffma2(acc[7][3], wD.y, v3);
            }

            // ---- consume high corners -> STS ----
            if (hasNext) {
                svn[4][tid] = nw00 * ch00.x + nw01 * ch01.x + nw10 * ch10.x + nw11 * ch11.x;
                svn[5][tid] = nw00 * ch00.y + nw01 * ch01.y + nw10 * ch10.y + nw11 * ch11.y;
                svn[6][tid] = nw00 * ch00.z + nw01 * ch01.z + nw10 * ch10.z + nw11 * ch11.z;
                svn[7][tid] = nw00 * ch00.w + nw01 * ch01.w + nw10 * ch10.w + nw11 * ch11.w;
            }

            __syncthreads();   // svn ready for next B; svb free for overwrite
        }
    }

    // Writeout: thread owns co [coStart, coStart+16) x px [pxBase, pxBase+4).
    const int r  = pxBase >> 5;
    const int cc = pxBase & 31;
    const size_t rowOff = (size_t)(hoBase + r) * WOn + (woBase + cc);
#pragma unroll
    for (int p = 0; p < 8; ++p) {
        float lo0, hi0, lo1, hi1, lo2, hi2, lo3, hi3;
        unpack2(acc[p][0], lo0, hi0);
        unpack2(acc[p][1], lo1, hi1);
        unpack2(acc[p][2], lo2, hi2);
        unpack2(acc[p][3], lo3, hi3);
        const int co = coStart + p * 2;
        *(float4*)&y[((size_t)(b * COUT + co)) * HWo + rowOff] =
            make_float4(lo0, lo1, lo2, lo3);
        *(float4*)&y[((size_t)(b * COUT + co + 1)) * HWo + rowOff] =
            make_float4(hi0, hi1, hi2, hi3);
    }
}

// ---------------------------------------------------------------------------
extern "C" void kernel_launch(void* const* d_in, const int* in_sizes, int n_in,
                              void* d_out, int out_size)
{
    const float* x  = (const float*)d_in[0];
    const float* w1 = (const float*)d_in[1];
    const float* b1 = (const float*)d_in[2];
    const float* w2 = (const float*)d_in[3];
    const float* b2 = (const float*)d_in[4];
    const float* wd = (const float*)d_in[5];

    float* y   = (float*)d_out;
    float* off = y + (size_t)Bn * COUT * HOn * WOn;   // off is output #2

    transpose_kernel<<<dim3(Hn, Gn, Bn), 256>>>(x);
    conv3x3_kernel<<<dim3(4, 8, Bn * 4), dim3(32, 8)>>>(x, w1, b1);
    conv1x1_kernel<<<dim3((Bn * HWo) / 256, 3), 256>>>(w2, b2, off);
    deform_kernel<<<dim3(WOn / 32, HOn / 8, Bn), 256>>>(wd, off, y);
}